// round 1
// baseline (speedup 1.0000x reference)
#include <cuda_runtime.h>

// Problem constants (match reference_code)
#define B_ 16
#define R_ 4
#define S_ 4
#define T_ 14
#define F_ 2048
#define NTF (T_ * F_)
#define NRE (B_ * NTF)

// ---------------- tiny complex helpers (register-resident) ----------------
struct cf { float re, im; };

__device__ __forceinline__ cf cadd(cf a, cf b) { return {a.re + b.re, a.im + b.im}; }
__device__ __forceinline__ cf csub(cf a, cf b) { return {a.re - b.re, a.im - b.im}; }
__device__ __forceinline__ cf cmul(cf a, cf b) {
    return {a.re * b.re - a.im * b.im, a.re * b.im + a.im * b.re};
}
// conj(a) * b
__device__ __forceinline__ cf cmulc(cf a, cf b) {
    return {a.re * b.re + a.im * b.im, a.re * b.im - a.im * b.re};
}
__device__ __forceinline__ cf cscale(cf a, float s) { return {a.re * s, a.im * s}; }
__device__ __forceinline__ cf cconj(cf a) { return {a.re, -a.im}; }
__device__ __forceinline__ float cabs2(cf a) { return a.re * a.re + a.im * a.im; }

// ---------------- one SIC step, trailing (N x N) Hermitian solve ----------------
// A = G[k:,k:] + no*I, k = 4-N. Computes:
//   u0   = (A^{-1} z_sub)[0]
//   a00  = (A^{-1})[0,0]          (real)
//   d    = 1 - no*a00
//   x_k  = u0 / d,  ne_k = no*a00 / d
// then SIC-updates z[s] -= G[s][k] * x_k for s > k.
template <int N>
__device__ __forceinline__ void sic_step(const cf G[4][4], cf z[4], float no,
                                         float m, cf* xout, float* nout) {
    constexpr int k = 4 - N;
    cf L[N][N];       // lower Cholesky factor (diag imag unused)
    float dinv[N];    // 1 / L[j][j]

    // Cholesky A = L L^H
#pragma unroll
    for (int j = 0; j < N; j++) {
        float djj = G[k + j][k + j].re + no;
#pragma unroll
        for (int p = 0; p < j; p++) djj -= cabs2(L[j][p]);
        float ljj = sqrtf(djj);
        float inv = 1.0f / ljj;
        dinv[j] = inv;
        L[j][j].re = ljj; L[j][j].im = 0.0f;
#pragma unroll
        for (int i = j + 1; i < N; i++) {
            cf acc = G[k + i][k + j];  // A[i][j], i>j (Hermitian full store)
#pragma unroll
            for (int p = 0; p < j; p++) acc = csub(acc, cmul(L[i][p], cconj(L[j][p])));
            L[i][j] = cscale(acc, inv);
        }
    }

    // forward solve L v = z_sub
    cf v[N];
#pragma unroll
    for (int i = 0; i < N; i++) {
        cf acc = z[k + i];
#pragma unroll
        for (int j = 0; j < i; j++) acc = csub(acc, cmul(L[i][j], v[j]));
        v[i] = cscale(acc, dinv[i]);
    }

    // backward solve L^H u = v (need u[0])
    cf u[N];
#pragma unroll
    for (int i = N - 1; i >= 0; i--) {
        cf acc = v[i];
#pragma unroll
        for (int j = i + 1; j < N; j++) acc = csub(acc, cmul(cconj(L[j][i]), u[j]));
        u[i] = cscale(acc, dinv[i]);
    }

    // first column of L^{-1}: L c = e0; (A^{-1})[0,0] = ||c||^2
    cf c[N];
    c[0].re = dinv[0]; c[0].im = 0.0f;
    float a00 = dinv[0] * dinv[0];
#pragma unroll
    for (int i = 1; i < N; i++) {
        cf acc = {0.0f, 0.0f};
#pragma unroll
        for (int j = 0; j < i; j++) acc = cadd(acc, cmul(L[i][j], c[j]));
        c[i] = cscale(acc, -dinv[i]);
        a00 += cabs2(c[i]);
    }

    float noa = no * a00;
    float dk = 1.0f - noa;
    float invd = 1.0f / dk;
    cf xk = cscale(u[0], invd);
    float ne = noa * invd;

    // SIC update on matched-filter outputs: z'[s] = z[s] - G[s][k] * xk
#pragma unroll
    for (int s = k + 1; s < 4; s++) z[s] = csub(z[s], cmul(G[s][k], xk));

    *xout = cscale(xk, m);
    *nout = ne * m;
}

// ---------------- main kernel: one thread per RE ----------------
__global__ void __launch_bounds__(256)
sic_lmmse_kernel(const float* __restrict__ yre, const float* __restrict__ yim,
                 const float* __restrict__ hre, const float* __restrict__ him,
                 const int* __restrict__ mask, const float* __restrict__ nv,
                 float* __restrict__ out) {
    int tid = blockIdx.x * blockDim.x + threadIdx.x;
    if (tid >= NRE) return;

    int b = tid / NTF;
    int tf = tid - b * NTF;  // t*F + f

    float no = nv[0];
    float m = (float)mask[tf];

    // Load y [R] and h [R][S] (all streams coalesced along f)
    cf y[4], h[4][4];
#pragma unroll
    for (int r = 0; r < 4; r++) {
        int yi = (b * 4 + r) * NTF + tf;
        y[r].re = yre[yi];
        y[r].im = yim[yi];
#pragma unroll
        for (int s = 0; s < 4; s++) {
            int hi = ((b * 4 + r) * 4 + s) * NTF + tf;
            h[r][s].re = hre[hi];
            h[r][s].im = him[hi];
        }
    }

    // Gram G = H^H H (Hermitian, stored full) and matched filter z = H^H y.
    // After this, h/y are dead — registers recycle.
    cf G[4][4], z[4];
#pragma unroll
    for (int s = 0; s < 4; s++) {
#pragma unroll
        for (int u2 = s; u2 < 4; u2++) {
            cf acc = {0.0f, 0.0f};
#pragma unroll
            for (int r = 0; r < 4; r++) acc = cadd(acc, cmulc(h[r][s], h[r][u2]));
            G[s][u2] = acc;
            G[u2][s] = cconj(acc);
        }
        cf zz = {0.0f, 0.0f};
#pragma unroll
        for (int r = 0; r < 4; r++) zz = cadd(zz, cmulc(h[r][s], y[r]));
        z[s] = zz;
    }

    cf x[4];
    float ne[4];
    sic_step<4>(G, z, no, m, &x[0], &ne[0]);
    sic_step<3>(G, z, no, m, &x[1], &ne[1]);
    sic_step<2>(G, z, no, m, &x[2], &ne[2]);
    sic_step<1>(G, z, no, m, &x[3], &ne[3]);

    // Output: x_ri [2,B,S,T,F] then no_eff [B,S,T,F], concatenated.
    const int X = B_ * S_ * NTF;  // 1,835,008
#pragma unroll
    for (int s = 0; s < 4; s++) {
        int base = (b * 4 + s) * NTF + tf;
        out[base] = x[s].re;          // real plane
        out[X + base] = x[s].im;      // imag plane
        out[2 * X + base] = ne[s];    // effective noise
    }
}

extern "C" void kernel_launch(void* const* d_in, const int* in_sizes, int n_in,
                              void* d_out, int out_size) {
    const float* y_re = (const float*)d_in[0];
    const float* y_im = (const float*)d_in[1];
    const float* h_re = (const float*)d_in[2];
    const float* h_im = (const float*)d_in[3];
    const int* mask = (const int*)d_in[4];
    const float* noise_var = (const float*)d_in[5];
    float* out = (float*)d_out;

    const int threads = 256;
    const int blocks = (NRE + threads - 1) / threads;
    sic_lmmse_kernel<<<blocks, threads>>>(y_re, y_im, h_re, h_im, mask, noise_var, out);
}

// round 2
// speedup vs baseline: 1.2746x; 1.2746x over previous
#include <cuda_runtime.h>

// Problem constants (match reference_code)
#define B_ 16
#define R_ 4
#define S_ 4
#define T_ 14
#define F_ 2048
#define NTF (T_ * F_)
#define NRE (B_ * NTF)

// ---------------- tiny complex helpers (register-resident) ----------------
struct cf { float re, im; };

__device__ __forceinline__ cf cadd(cf a, cf b) { return {a.re + b.re, a.im + b.im}; }
__device__ __forceinline__ cf csub(cf a, cf b) { return {a.re - b.re, a.im - b.im}; }
__device__ __forceinline__ cf cmul(cf a, cf b) {
    return {a.re * b.re - a.im * b.im, a.re * b.im + a.im * b.re};
}
// conj(a) * b
__device__ __forceinline__ cf cmulc(cf a, cf b) {
    return {a.re * b.re + a.im * b.im, a.re * b.im - a.im * b.re};
}
// a - b * conj(c)
__device__ __forceinline__ cf csub_mulc2(cf a, cf b, cf c) {
    return {a.re - (b.re * c.re + b.im * c.im), a.im - (b.im * c.re - b.re * c.im)};
}
__device__ __forceinline__ cf cscale(cf a, float s) { return {a.re * s, a.im * s}; }
__device__ __forceinline__ float cabs2(cf a) { return a.re * a.re + a.im * a.im; }

// ---------------- main kernel: one thread per RE ----------------
__global__ void __launch_bounds__(256)
sic_lmmse_kernel(const float* __restrict__ yre, const float* __restrict__ yim,
                 const float* __restrict__ hre, const float* __restrict__ him,
                 const int* __restrict__ mask, const float* __restrict__ nv,
                 float* __restrict__ out) {
    int tid = blockIdx.x * blockDim.x + threadIdx.x;  // grid is exact: NRE = 1792*256

    int b = tid / NTF;
    int tf = tid - b * NTF;  // t*F + f

    float no = nv[0];
    float m = (float)mask[tf];

    // ---- front-batched loads: y [R], h [R][S] (coalesced along f, MLP=40) ----
    cf y[4], h[4][4];
#pragma unroll
    for (int r = 0; r < 4; r++) {
        int yi = (b * 4 + r) * NTF + tf;
        y[r].re = yre[yi];
        y[r].im = yim[yi];
#pragma unroll
        for (int s = 0; s < 4; s++) {
            int hi = ((b * 4 + r) * 4 + s) * NTF + tf;
            h[r][s].re = hre[hi];
            h[r][s].im = him[hi];
        }
    }

    // ---- Gram (upper triangle + real diagonal) and matched filter z = H^H y ----
    float Gd[4];     // real diagonal of G
    cf G01, G02, G03, G12, G13, G23;
    cf z[4];
#pragma unroll
    for (int s = 0; s < 4; s++) {
        float d = 0.0f;
#pragma unroll
        for (int r = 0; r < 4; r++) d += cabs2(h[r][s]);
        Gd[s] = d;
        cf zz = {0.0f, 0.0f};
#pragma unroll
        for (int r = 0; r < 4; r++) zz = cadd(zz, cmulc(h[r][s], y[r]));
        z[s] = zz;
    }
    {
        cf a01 = {0,0}, a02 = {0,0}, a03 = {0,0}, a12 = {0,0}, a13 = {0,0}, a23 = {0,0};
#pragma unroll
        for (int r = 0; r < 4; r++) {
            a01 = cadd(a01, cmulc(h[r][0], h[r][1]));
            a02 = cadd(a02, cmulc(h[r][0], h[r][2]));
            a03 = cadd(a03, cmulc(h[r][0], h[r][3]));
            a12 = cadd(a12, cmulc(h[r][1], h[r][2]));
            a13 = cadd(a13, cmulc(h[r][1], h[r][3]));
            a23 = cadd(a23, cmulc(h[r][2], h[r][3]));
        }
        G01 = a01; G02 = a02; G03 = a03; G12 = a12; G13 = a13; G23 = a23;
    }

    // ---- reverse Cholesky: A = G + no*I = U U^H, U upper triangular.
    // Nested property: A[k:,k:] = U[k:,k:] U[k:,k:]^H for all k, so ONE
    // factorization serves all four SIC steps, and (A_k^{-1})_00 = dinv[k]^2.
    float dinv0, dinv1, dinv2, dinv3;
    cf U01, U02, U03, U12, U13, U23;

    float t3 = Gd[3] + no;
    dinv3 = rsqrtf(t3);
    U23 = cscale(G23, dinv3);
    U13 = cscale(G13, dinv3);
    U03 = cscale(G03, dinv3);

    float t2 = Gd[2] + no - cabs2(U23);
    dinv2 = rsqrtf(t2);
    U12 = cscale(csub_mulc2(G12, U13, U23), dinv2);
    U02 = cscale(csub_mulc2(G02, U03, U23), dinv2);

    float t1 = Gd[1] + no - cabs2(U12) - cabs2(U13);
    dinv1 = rsqrtf(t1);
    U01 = cscale(csub_mulc2(csub_mulc2(G01, U02, U12), U03, U13), dinv1);

    float t0 = Gd[0] + no - cabs2(U01) - cabs2(U02) - cabs2(U03);
    dinv0 = rsqrtf(t0);

    // ---- one backward solve: w = U^{-1} z ----
    cf w3 = cscale(z[3], dinv3);
    cf w2 = cscale(csub(z[2], cmul(U23, w3)), dinv2);
    cf w1 = cscale(csub(csub(z[1], cmul(U12, w2)), cmul(U13, w3)), dinv1);
    cf w0 = cscale(csub(csub(csub(z[0], cmul(U01, w1)), cmul(U02, w2)), cmul(U03, w3)), dinv0);

    // ---- 4 SIC steps, each O(1): bias correction + rank-1 w update ----
    cf x[4];
    float ne[4];

    // k = 0
    {
        float a = dinv0 * dinv0;
        float noa = no * a;
        float idk = __fdividef(1.0f, 1.0f - noa);
        cf xk = cscale(w0, dinv0 * idk);
        ne[0] = noa * idk;
        x[0] = xk;
        w1 = csub_mulc2(w1, xk, U01);  // w1 -= xk * conj(U01)
        w2 = csub_mulc2(w2, xk, U02);
        w3 = csub_mulc2(w3, xk, U03);
    }
    // k = 1
    {
        float a = dinv1 * dinv1;
        float noa = no * a;
        float idk = __fdividef(1.0f, 1.0f - noa);
        cf xk = cscale(w1, dinv1 * idk);
        ne[1] = noa * idk;
        x[1] = xk;
        w2 = csub_mulc2(w2, xk, U12);
        w3 = csub_mulc2(w3, xk, U13);
    }
    // k = 2
    {
        float a = dinv2 * dinv2;
        float noa = no * a;
        float idk = __fdividef(1.0f, 1.0f - noa);
        cf xk = cscale(w2, dinv2 * idk);
        ne[2] = noa * idk;
        x[2] = xk;
        w3 = csub_mulc2(w3, xk, U23);
    }
    // k = 3
    {
        float a = dinv3 * dinv3;
        float noa = no * a;
        float idk = __fdividef(1.0f, 1.0f - noa);
        x[3] = cscale(w3, dinv3 * idk);
        ne[3] = noa * idk;
    }

    // ---- output: x_ri [2,B,S,T,F] then no_eff [B,S,T,F], concatenated ----
    const int X = B_ * S_ * NTF;  // 1,835,008
#pragma unroll
    for (int s = 0; s < 4; s++) {
        int base = (b * 4 + s) * NTF + tf;
        out[base] = x[s].re * m;
        out[X + base] = x[s].im * m;
        out[2 * X + base] = ne[s] * m;
    }
}

extern "C" void kernel_launch(void* const* d_in, const int* in_sizes, int n_in,
                              void* d_out, int out_size) {
    const float* y_re = (const float*)d_in[0];
    const float* y_im = (const float*)d_in[1];
    const float* h_re = (const float*)d_in[2];
    const float* h_im = (const float*)d_in[3];
    const int* mask = (const int*)d_in[4];
    const float* noise_var = (const float*)d_in[5];
    float* out = (float*)d_out;

    const int threads = 256;
    const int blocks = NRE / threads;  // exact: 458752 / 256 = 1792
    sic_lmmse_kernel<<<blocks, threads>>>(y_re, y_im, h_re, h_im, mask, noise_var, out);
}

// round 3
// speedup vs baseline: 1.4567x; 1.1429x over previous
#include <cuda_runtime.h>

// Problem constants (match reference_code)
#define B_ 16
#define R_ 4
#define S_ 4
#define T_ 14
#define F_ 2048
#define NTF (T_ * F_)
#define NRE (B_ * NTF)

typedef unsigned long long ull;

// ================= packed f32x2 primitives (sm_100+ PTX only) =================
__device__ __forceinline__ ull padd(ull a, ull b) {
    ull r; asm("add.rn.f32x2 %0,%1,%2;" : "=l"(r) : "l"(a), "l"(b)); return r;
}
__device__ __forceinline__ ull psub(ull a, ull b) {
    ull r; asm("sub.rn.f32x2 %0,%1,%2;" : "=l"(r) : "l"(a), "l"(b)); return r;
}
__device__ __forceinline__ ull pmul(ull a, ull b) {
    ull r; asm("mul.rn.f32x2 %0,%1,%2;" : "=l"(r) : "l"(a), "l"(b)); return r;
}
// a*b + c
__device__ __forceinline__ ull pfma(ull a, ull b, ull c) {
    ull r; asm("fma.rn.f32x2 %0,%1,%2,%3;" : "=l"(r) : "l"(a), "l"(b), "l"(c)); return r;
}
__device__ __forceinline__ ull pk(float lo, float hi) {
    ull r;
    asm("mov.b64 %0,{%1,%2};" : "=l"(r) : "r"(__float_as_uint(lo)), "r"(__float_as_uint(hi)));
    return r;
}
__device__ __forceinline__ void upk(ull v, float& lo, float& hi) {
    unsigned ul, uh;
    asm("mov.b64 {%0,%1},%2;" : "=r"(ul), "=r"(uh) : "l"(v));
    lo = __uint_as_float(ul); hi = __uint_as_float(uh);
}
// per-lane rsqrt / reciprocal (MUFU)
__device__ __forceinline__ ull prsqrt(ull v) {
    float lo, hi; upk(v, lo, hi);
    return pk(rsqrtf(lo), rsqrtf(hi));
}
__device__ __forceinline__ ull prcp(ull v) {
    float lo, hi; upk(v, lo, hi);
    return pk(__fdividef(1.0f, lo), __fdividef(1.0f, hi));
}

// ================= packed complex (each component is a {f,f+1} pair) =========
struct c2 { ull re, im; };

__device__ __forceinline__ c2 cscale2(c2 a, ull s) { return {pmul(a.re, s), pmul(a.im, s)}; }
__device__ __forceinline__ ull cabs2_2(c2 a) { return pfma(a.im, a.im, pmul(a.re, a.re)); }
// a - b*c   (7 packed ops)
__device__ __forceinline__ c2 csub_mul(c2 a, c2 b, c2 c) {
    ull re = pfma(b.im, c.im, psub(a.re, pmul(b.re, c.re)));
    ull im = psub(psub(a.im, pmul(b.re, c.im)), pmul(b.im, c.re));
    return {re, im};
}
// a - b*conj(c)  (6 packed ops)
__device__ __forceinline__ c2 csub_mulc(c2 a, c2 b, c2 c) {
    ull re = psub(a.re, pfma(b.re, c.re, pmul(b.im, c.im)));
    ull im = pfma(b.re, c.im, psub(a.im, pmul(b.im, c.re)));
    return {re, im};
}

// ================= main kernel: one thread per PAIR of REs ====================
__global__ void __launch_bounds__(256, 2)
sic_lmmse_kernel(const float* __restrict__ yre, const float* __restrict__ yim,
                 const float* __restrict__ hre, const float* __restrict__ him,
                 const int* __restrict__ mask, const float* __restrict__ nv,
                 float* __restrict__ out) {
    const int NP = NTF / 2;  // RE pairs per batch element
    int tid = blockIdx.x * blockDim.x + threadIdx.x;  // exact grid: NRE/2 threads
    int b = tid / NP;
    int tf = (tid - b * NP) * 2;  // even -> 8B-aligned float2 accesses

    float no = nv[0];
    ull no2 = pk(no, no);
    const ull ZERO = 0ULL;                  // {0.f, 0.f}
    const ull ONE2 = 0x3F8000003F800000ULL; // {1.f, 1.f}

    // mask pair -> packed float
    int2 mi = *reinterpret_cast<const int2*>(mask + tf);
    ull m2 = pk((float)mi.x, (float)mi.y);

    int ybase = b * 4 * NTF + tf;
    int hbase = b * 16 * NTF + tf;

    // ---- Gram accumulators (upper tri + real diag) and matched filter z ----
    ull Gd0 = 0, Gd1 = 0, Gd2 = 0, Gd3 = 0;
    c2 G01 = {0, 0}, G02 = {0, 0}, G03 = {0, 0}, G12 = {0, 0}, G13 = {0, 0}, G23 = {0, 0};
    c2 z0 = {0, 0}, z1 = {0, 0}, z2 = {0, 0}, z3 = {0, 0};

#pragma unroll
    for (int r = 0; r < 4; r++) {
        ull Yr = *reinterpret_cast<const ull*>(yre + ybase + r * NTF);
        ull Yi = *reinterpret_cast<const ull*>(yim + ybase + r * NTF);
        ull hr[4], hi[4], ni[4];
#pragma unroll
        for (int s = 0; s < 4; s++) {
            hr[s] = *reinterpret_cast<const ull*>(hre + hbase + (r * 4 + s) * NTF);
            hi[s] = *reinterpret_cast<const ull*>(him + hbase + (r * 4 + s) * NTF);
        }
#pragma unroll
        for (int s = 0; s < 4; s++) ni[s] = psub(ZERO, hi[s]);  // -im, keeps FMAs pure

        // diagonals: Gd[s] += |h_s|^2
        Gd0 = pfma(hr[0], hr[0], pfma(hi[0], hi[0], Gd0));
        Gd1 = pfma(hr[1], hr[1], pfma(hi[1], hi[1], Gd1));
        Gd2 = pfma(hr[2], hr[2], pfma(hi[2], hi[2], Gd2));
        Gd3 = pfma(hr[3], hr[3], pfma(hi[3], hi[3], Gd3));

        // off-diagonals: G[s][u] += conj(h_s) * h_u
        //   re += h_s.re*h_u.re + h_s.im*h_u.im ;  im += h_s.re*h_u.im + (-h_s.im)*h_u.re
#define CMAC(ACC, S, U)                                                      \
        ACC.re = pfma(hr[S], hr[U], pfma(hi[S], hi[U], ACC.re));             \
        ACC.im = pfma(hr[S], hi[U], pfma(ni[S], hr[U], ACC.im));
        CMAC(G01, 0, 1) CMAC(G02, 0, 2) CMAC(G03, 0, 3)
        CMAC(G12, 1, 2) CMAC(G13, 1, 3) CMAC(G23, 2, 3)
#undef CMAC

        // z[s] += conj(h_s) * y
#define ZMAC(ACC, S)                                                         \
        ACC.re = pfma(hr[S], Yr, pfma(hi[S], Yi, ACC.re));                   \
        ACC.im = pfma(hr[S], Yi, pfma(ni[S], Yr, ACC.im));
        ZMAC(z0, 0) ZMAC(z1, 1) ZMAC(z2, 2) ZMAC(z3, 3)
#undef ZMAC
    }

    // ---- reverse Cholesky: A = G + no*I = U U^H (U upper). Nested property:
    // A[k:,k:] = U[k:,k:] U[k:,k:]^H, so ONE factorization serves all 4 SIC steps,
    // and (A_k^{-1})_00 = dinv[k]^2.
    ull t3 = padd(Gd3, no2);
    ull dinv3 = prsqrt(t3);
    c2 U23 = cscale2(G23, dinv3);
    c2 U13 = cscale2(G13, dinv3);
    c2 U03 = cscale2(G03, dinv3);

    ull t2 = psub(padd(Gd2, no2), cabs2_2(U23));
    ull dinv2 = prsqrt(t2);
    c2 U12 = cscale2(csub_mulc(G12, U13, U23), dinv2);
    c2 U02 = cscale2(csub_mulc(G02, U03, U23), dinv2);

    ull t1 = psub(psub(padd(Gd1, no2), cabs2_2(U12)), cabs2_2(U13));
    ull dinv1 = prsqrt(t1);
    c2 U01 = cscale2(csub_mulc(csub_mulc(G01, U02, U12), U03, U13), dinv1);

    ull t0 = psub(psub(psub(padd(Gd0, no2), cabs2_2(U01)), cabs2_2(U02)), cabs2_2(U03));
    ull dinv0 = prsqrt(t0);

    // ---- one backward solve: w = U^{-1} z ----
    c2 w3 = cscale2(z3, dinv3);
    c2 w2 = cscale2(csub_mul(z2, U23, w3), dinv2);
    c2 w1 = cscale2(csub_mul(csub_mul(z1, U12, w2), U13, w3), dinv1);
    c2 w0 = cscale2(csub_mul(csub_mul(csub_mul(z0, U01, w1), U02, w2), U03, w3), dinv0);

    // ---- 4 SIC steps, each O(1): bias correction + rank-1 w update ----
    c2 x0, x1, x2, x3;
    ull ne0, ne1, ne2, ne3;

    {   // k = 0
        ull noa = pmul(no2, pmul(dinv0, dinv0));
        ull idk = prcp(psub(ONE2, noa));
        c2 xk = cscale2(w0, pmul(dinv0, idk));
        ne0 = pmul(noa, idk);
        x0 = xk;
        w1 = csub_mulc(w1, xk, U01);
        w2 = csub_mulc(w2, xk, U02);
        w3 = csub_mulc(w3, xk, U03);
    }
    {   // k = 1
        ull noa = pmul(no2, pmul(dinv1, dinv1));
        ull idk = prcp(psub(ONE2, noa));
        c2 xk = cscale2(w1, pmul(dinv1, idk));
        ne1 = pmul(noa, idk);
        x1 = xk;
        w2 = csub_mulc(w2, xk, U12);
        w3 = csub_mulc(w3, xk, U13);
    }
    {   // k = 2
        ull noa = pmul(no2, pmul(dinv2, dinv2));
        ull idk = prcp(psub(ONE2, noa));
        c2 xk = cscale2(w2, pmul(dinv2, idk));
        ne2 = pmul(noa, idk);
        x2 = xk;
        w3 = csub_mulc(w3, xk, U23);
    }
    {   // k = 3
        ull noa = pmul(no2, pmul(dinv3, dinv3));
        ull idk = prcp(psub(ONE2, noa));
        x3 = cscale2(w3, pmul(dinv3, idk));
        ne3 = pmul(noa, idk);
    }

    // ---- output: x_ri [2,B,S,T,F] then no_eff [B,S,T,F]; packed 8B stores ----
    const int X = B_ * S_ * NTF;  // 1,835,008
    c2 xs[4] = {x0, x1, x2, x3};
    ull nes[4] = {ne0, ne1, ne2, ne3};
#pragma unroll
    for (int s = 0; s < 4; s++) {
        int base = (b * 4 + s) * NTF + tf;
        *reinterpret_cast<ull*>(out + base)         = pmul(xs[s].re, m2);
        *reinterpret_cast<ull*>(out + X + base)     = pmul(xs[s].im, m2);
        *reinterpret_cast<ull*>(out + 2 * X + base) = pmul(nes[s], m2);
    }
}

extern "C" void kernel_launch(void* const* d_in, const int* in_sizes, int n_in,
                              void* d_out, int out_size) {
    const float* y_re = (const float*)d_in[0];
    const float* y_im = (const float*)d_in[1];
    const float* h_re = (const float*)d_in[2];
    const float* h_im = (const float*)d_in[3];
    const int* mask = (const int*)d_in[4];
    const float* noise_var = (const float*)d_in[5];
    float* out = (float*)d_out;

    const int threads = 256;
    const int blocks = (NRE / 2) / threads;  // exact: 229376 / 256 = 896
    sic_lmmse_kernel<<<blocks, threads>>>(y_re, y_im, h_re, h_im, mask, noise_var, out);
}